// round 1
// baseline (speedup 1.0000x reference)
#include <cuda_runtime.h>
#include <cstdint>

#define EPSF 1e-6f

static constexpr int BATCH = 8;
static constexpr int NSEQ  = 4096;
static constexpr int DIM   = 1024;
static constexpr int MTOT  = BATCH * NSEQ;   // 32768
static constexpr int QKVW  = 3 * DIM;        // 3072

// ---------------- scratch (alloc-free rule: __device__ globals) ----------------
__device__ float g_qkv [(size_t)MTOT * QKVW];     // ~402 MB
__device__ float g_kvT [(size_t)BATCH * DIM * DIM];
__device__ float g_attn[(size_t)MTOT * DIM];
__device__ float g_ksum[BATCH * DIM];
__device__ float g_z   [MTOT];

// ---------------- tf32 helpers ----------------
__device__ __forceinline__ uint32_t f2tf32(float f) {
    uint32_t r;
    asm("cvt.rna.tf32.f32 %0, %1;" : "=r"(r) : "f"(f));
    return r;
}

__device__ __forceinline__ void mma_tf32(float c[4],
                                         uint32_t a0, uint32_t a1, uint32_t a2, uint32_t a3,
                                         uint32_t b0, uint32_t b1) {
    asm volatile(
        "mma.sync.aligned.m16n8k8.row.col.f32.tf32.tf32.f32 "
        "{%0,%1,%2,%3},{%4,%5,%6,%7},{%8,%9},{%0,%1,%2,%3};\n"
        : "+f"(c[0]), "+f"(c[1]), "+f"(c[2]), "+f"(c[3])
        : "r"(a0), "r"(a1), "r"(a2), "r"(a3), "r"(b0), "r"(b1));
}

// ---------------- epilogue ----------------
template<bool RELU, bool SCALE, bool BIAS>
__device__ __forceinline__ void store_pair(float* C, int ldc, int row, int col,
                                           float v0, float v1,
                                           const float* rowScale, const float* bias) {
    if (SCALE) { float s = rowScale[row]; v0 *= s; v1 *= s; }
    if (RELU) {
        if (col < 2 * DIM) {            // q and k segments get relu + eps; v untouched
            v0 = fmaxf(v0, 0.f) + EPSF;
            v1 = fmaxf(v1, 0.f) + EPSF;
        }
    }
    if (BIAS) { v0 += bias[col]; v1 += bias[col + 1]; }
    *reinterpret_cast<float2*>(C + (long long)row * ldc + col) = make_float2(v0, v1);
}

// =====================================================================
// NT GEMM: C[M,N] = A[M,K] (row-major, lda) * Bt[N,K]^T (row-major, ldb)
// Block tile 128x128, BK=16, 8 warps (2x4), warp tile 64x32.
// tf32x3 split for ~fp32 accuracy.
// =====================================================================
#define BM 128
#define BN 128
#define BK 16
#define LDS_NT (BK + 4)     // 20 floats: conflict-free, 16B-aligned rows (80B)

template<bool RELU, bool SCALE, bool BIAS>
__global__ __launch_bounds__(256, 2)
void gemm_nt(const float* __restrict__ A, int lda, long long strideA,
             const float* __restrict__ Bt, int ldb, long long strideB,
             float* __restrict__ C, int ldc, long long strideC,
             int K,
             const float* __restrict__ rowScale, long long strideScale,
             const float* __restrict__ bias)
{
    __shared__ uint32_t AsH[BM][LDS_NT], AsL[BM][LDS_NT];
    __shared__ uint32_t BsH[BN][LDS_NT], BsL[BN][LDS_NT];

    const int tid  = threadIdx.x;
    const int wid  = tid >> 5;
    const int lane = tid & 31;
    const int g    = lane >> 2;      // groupID
    const int t    = lane & 3;       // thread-in-group
    const int warpM = (wid >> 2) * 64;
    const int warpN = (wid & 3) * 32;
    const int m0 = blockIdx.y * BM;
    const int n0 = blockIdx.x * BN;
    const int bz = blockIdx.z;

    A  += (long long)bz * strideA;
    Bt += (long long)bz * strideB;
    C  += (long long)bz * strideC;
    if (SCALE) rowScale += (long long)bz * strideScale;

    float acc[4][4][4];
    #pragma unroll
    for (int i = 0; i < 4; i++)
        #pragma unroll
        for (int j = 0; j < 4; j++)
            #pragma unroll
            for (int r = 0; r < 4; r++) acc[i][j][r] = 0.f;

    for (int kt = 0; kt < K; kt += BK) {
        // Load A & Bt tiles: each 128x16 = 512 float4, 256 threads -> 2 iters
        #pragma unroll
        for (int it = 0; it < 2; it++) {
            int i  = tid + it * 256;
            int m  = i >> 2;
            int k4 = (i & 3) * 4;
            float4 va = *reinterpret_cast<const float4*>(A + (long long)(m0 + m) * lda + kt + k4);
            float4 vb = *reinterpret_cast<const float4*>(Bt + (long long)(n0 + m) * ldb + kt + k4);
            float fa[4] = {va.x, va.y, va.z, va.w};
            float fb[4] = {vb.x, vb.y, vb.z, vb.w};
            uint32_t ah[4], al[4], bh[4], bl[4];
            #pragma unroll
            for (int j = 0; j < 4; j++) {
                ah[j] = f2tf32(fa[j]); al[j] = f2tf32(fa[j] - __uint_as_float(ah[j]));
                bh[j] = f2tf32(fb[j]); bl[j] = f2tf32(fb[j] - __uint_as_float(bh[j]));
            }
            *reinterpret_cast<uint4*>(&AsH[m][k4]) = make_uint4(ah[0], ah[1], ah[2], ah[3]);
            *reinterpret_cast<uint4*>(&AsL[m][k4]) = make_uint4(al[0], al[1], al[2], al[3]);
            *reinterpret_cast<uint4*>(&BsH[m][k4]) = make_uint4(bh[0], bh[1], bh[2], bh[3]);
            *reinterpret_cast<uint4*>(&BsL[m][k4]) = make_uint4(bl[0], bl[1], bl[2], bl[3]);
        }
        __syncthreads();

        #pragma unroll
        for (int kk = 0; kk < BK; kk += 8) {
            uint32_t ah[4][4], al[4][4];
            #pragma unroll
            for (int mi = 0; mi < 4; mi++) {
                int r = warpM + mi * 16 + g;
                ah[mi][0] = AsH[r    ][kk + t];
                ah[mi][1] = AsH[r + 8][kk + t];
                ah[mi][2] = AsH[r    ][kk + t + 4];
                ah[mi][3] = AsH[r + 8][kk + t + 4];
                al[mi][0] = AsL[r    ][kk + t];
                al[mi][1] = AsL[r + 8][kk + t];
                al[mi][2] = AsL[r    ][kk + t + 4];
                al[mi][3] = AsL[r + 8][kk + t + 4];
            }
            #pragma unroll
            for (int ni = 0; ni < 4; ni++) {
                int c = warpN + ni * 8 + g;
                uint32_t bh0 = BsH[c][kk + t], bh1 = BsH[c][kk + t + 4];
                uint32_t bl0 = BsL[c][kk + t], bl1 = BsL[c][kk + t + 4];
                #pragma unroll
                for (int mi = 0; mi < 4; mi++) {
                    mma_tf32(acc[mi][ni], ah[mi][0], ah[mi][1], ah[mi][2], ah[mi][3], bh0, bh1);
                    mma_tf32(acc[mi][ni], ah[mi][0], ah[mi][1], ah[mi][2], ah[mi][3], bl0, bl1);
                    mma_tf32(acc[mi][ni], al[mi][0], al[mi][1], al[mi][2], al[mi][3], bh0, bh1);
                }
            }
        }
        __syncthreads();
    }

    // Epilogue
    #pragma unroll
    for (int mi = 0; mi < 4; mi++) {
        int r0 = m0 + warpM + mi * 16 + g;
        #pragma unroll
        for (int ni = 0; ni < 4; ni++) {
            int c0 = n0 + warpN + ni * 8 + 2 * t;
            store_pair<RELU, SCALE, BIAS>(C, ldc, r0,     c0, acc[mi][ni][0], acc[mi][ni][1], rowScale, bias);
            store_pair<RELU, SCALE, BIAS>(C, ldc, r0 + 8, c0, acc[mi][ni][2], acc[mi][ni][3], rowScale, bias);
        }
    }
}

// =====================================================================
// TN GEMM: C[M,N] = sum_k A[k,M] * B[k,N]   (A,B row-major over k, lda/ldb)
// Used for kvT[e,d] = sum_n V[n,e] * K[n,d]
// =====================================================================
#define LDS_TN (BM + 8)   // 136: conflict-free, rows 544B = 34*16B

__global__ __launch_bounds__(256, 2)
void gemm_tn(const float* __restrict__ A, int lda, long long strideA,
             const float* __restrict__ B, int ldb, long long strideB,
             float* __restrict__ C, int ldc, long long strideC,
             int K)
{
    __shared__ uint32_t AsH[BK][LDS_TN], AsL[BK][LDS_TN];
    __shared__ uint32_t BsH[BK][LDS_TN], BsL[BK][LDS_TN];

    const int tid  = threadIdx.x;
    const int wid  = tid >> 5;
    const int lane = tid & 31;
    const int g    = lane >> 2;
    const int t    = lane & 3;
    const int warpM = (wid >> 2) * 64;
    const int warpN = (wid & 3) * 32;
    const int m0 = blockIdx.y * BM;
    const int n0 = blockIdx.x * BN;
    const int bz = blockIdx.z;

    A += (long long)bz * strideA;
    B += (long long)bz * strideB;
    C += (long long)bz * strideC;

    float acc[4][4][4];
    #pragma unroll
    for (int i = 0; i < 4; i++)
        #pragma unroll
        for (int j = 0; j < 4; j++)
            #pragma unroll
            for (int r = 0; r < 4; r++) acc[i][j][r] = 0.f;

    for (int kt = 0; kt < K; kt += BK) {
        // Tiles: 16 rows(k) x 128 cols(m/n) = 512 float4 each; 2 iters
        #pragma unroll
        for (int it = 0; it < 2; it++) {
            int i  = tid + it * 256;
            int k  = i >> 5;
            int m4 = (i & 31) * 4;
            float4 va = *reinterpret_cast<const float4*>(A + (long long)(kt + k) * lda + m0 + m4);
            float4 vb = *reinterpret_cast<const float4*>(B + (long long)(kt + k) * ldb + n0 + m4);
            float fa[4] = {va.x, va.y, va.z, va.w};
            float fb[4] = {vb.x, vb.y, vb.z, vb.w};
            uint32_t ah[4], al[4], bh[4], bl[4];
            #pragma unroll
            for (int j = 0; j < 4; j++) {
                ah[j] = f2tf32(fa[j]); al[j] = f2tf32(fa[j] - __uint_as_float(ah[j]));
                bh[j] = f2tf32(fb[j]); bl[j] = f2tf32(fb[j] - __uint_as_float(bh[j]));
            }
            *reinterpret_cast<uint4*>(&AsH[k][m4]) = make_uint4(ah[0], ah[1], ah[2], ah[3]);
            *reinterpret_cast<uint4*>(&AsL[k][m4]) = make_uint4(al[0], al[1], al[2], al[3]);
            *reinterpret_cast<uint4*>(&BsH[k][m4]) = make_uint4(bh[0], bh[1], bh[2], bh[3]);
            *reinterpret_cast<uint4*>(&BsL[k][m4]) = make_uint4(bl[0], bl[1], bl[2], bl[3]);
        }
        __syncthreads();

        #pragma unroll
        for (int kk = 0; kk < BK; kk += 8) {
            uint32_t ah[4][4], al[4][4];
            #pragma unroll
            for (int mi = 0; mi < 4; mi++) {
                int r = warpM + mi * 16 + g;
                ah[mi][0] = AsH[kk + t    ][r    ];
                ah[mi][1] = AsH[kk + t    ][r + 8];
                ah[mi][2] = AsH[kk + t + 4][r    ];
                ah[mi][3] = AsH[kk + t + 4][r + 8];
                al[mi][0] = AsL[kk + t    ][r    ];
                al[mi][1] = AsL[kk + t    ][r + 8];
                al[mi][2] = AsL[kk + t + 4][r    ];
                al[mi][3] = AsL[kk + t + 4][r + 8];
            }
            #pragma unroll
            for (int ni = 0; ni < 4; ni++) {
                int c = warpN + ni * 8 + g;
                uint32_t bh0 = BsH[kk + t][c], bh1 = BsH[kk + t + 4][c];
                uint32_t bl0 = BsL[kk + t][c], bl1 = BsL[kk + t + 4][c];
                #pragma unroll
                for (int mi = 0; mi < 4; mi++) {
                    mma_tf32(acc[mi][ni], ah[mi][0], ah[mi][1], ah[mi][2], ah[mi][3], bh0, bh1);
                    mma_tf32(acc[mi][ni], ah[mi][0], ah[mi][1], ah[mi][2], ah[mi][3], bl0, bl1);
                    mma_tf32(acc[mi][ni], al[mi][0], al[mi][1], al[mi][2], al[mi][3], bh0, bh1);
                }
            }
        }
        __syncthreads();
    }

    #pragma unroll
    for (int mi = 0; mi < 4; mi++) {
        int r0 = m0 + warpM + mi * 16 + g;
        #pragma unroll
        for (int ni = 0; ni < 4; ni++) {
            int c0 = n0 + warpN + ni * 8 + 2 * t;
            *reinterpret_cast<float2*>(C + (long long)r0 * ldc + c0) =
                make_float2(acc[mi][ni][0], acc[mi][ni][1]);
            *reinterpret_cast<float2*>(C + (long long)(r0 + 8) * ldc + c0) =
                make_float2(acc[mi][ni][2], acc[mi][ni][3]);
        }
    }
}

// ---------------- ksum[b,d] = sum_n k[b,n,d] (k = qkv cols [1024,2048)) ----------------
__global__ void ksum_kernel(const float* __restrict__ qkv, float* __restrict__ ksum)
{
    int d = blockIdx.x * 256 + threadIdx.x;
    int b = blockIdx.y;
    const float* base = qkv + (long long)b * NSEQ * QKVW + DIM + d;
    float s = 0.f;
    #pragma unroll 8
    for (int n = 0; n < NSEQ; n++) s += base[(long long)n * QKVW];
    ksum[b * DIM + d] = s;
}

// ---------------- z[b,n] = 1/(dot(q[b,n,:], ksum[b,:]) + eps) ----------------
__global__ void z_kernel(const float* __restrict__ qkv, const float* __restrict__ ksum,
                         float* __restrict__ z)
{
    int row  = blockIdx.x * 8 + (threadIdx.x >> 5);   // one warp per row
    int lane = threadIdx.x & 31;
    int b = row >> 12;                                 // row / 4096
    const float* q  = qkv + (long long)row * QKVW;     // q segment at col 0
    const float* ks = ksum + b * DIM;
    float s = 0.f;
    #pragma unroll 8
    for (int i = lane; i < DIM; i += 32) s += q[i] * ks[i];
    #pragma unroll
    for (int o = 16; o > 0; o >>= 1) s += __shfl_xor_sync(0xFFFFFFFFu, s, o);
    if (lane == 0) z[row] = 1.f / (s + EPSF);
}

// =====================================================================
extern "C" void kernel_launch(void* const* d_in, const int* in_sizes, int n_in,
                              void* d_out, int out_size)
{
    const float* x    = (const float*)d_in[0];   // [8,4096,1024]
    const float* Wqkv = (const float*)d_in[1];   // [3072,1024]
    const float* Wout = (const float*)d_in[2];   // [1024,1024]
    const float* bout = (const float*)d_in[3];   // [1024]
    float* out = (float*)d_out;                  // [8,4096,1024]

    float *qkv, *kvT, *attn, *ksum, *z;
    cudaGetSymbolAddress((void**)&qkv,  g_qkv);
    cudaGetSymbolAddress((void**)&kvT,  g_kvT);
    cudaGetSymbolAddress((void**)&attn, g_attn);
    cudaGetSymbolAddress((void**)&ksum, g_ksum);
    cudaGetSymbolAddress((void**)&z,    g_z);

    const long long sQKV = (long long)NSEQ * QKVW;   // per-batch qkv stride
    const long long sKV  = (long long)DIM * DIM;
    const long long sAT  = (long long)NSEQ * DIM;

    // 1) qkv = x @ Wqkv^T, relu+eps on q,k segments
    gemm_nt<true, false, false><<<dim3(QKVW / BN, MTOT / BM, 1), 256>>>(
        x, DIM, 0, Wqkv, DIM, 0, qkv, QKVW, 0, DIM, nullptr, 0, nullptr);

    // 2) ksum[b,d]
    ksum_kernel<<<dim3(DIM / 256, BATCH), 256>>>(qkv, ksum);

    // 3) kvT[b,e,d] = sum_n V[b,n,e] * K[b,n,d]   (TN, per batch)
    gemm_tn<<<dim3(DIM / BN, DIM / BM, BATCH), 256>>>(
        qkv + 2 * DIM, QKVW, sQKV,     // A = V
        qkv + DIM,     QKVW, sQKV,     // B = K
        kvT, DIM, sKV, NSEQ);

    // 4) z[b,n]
    z_kernel<<<MTOT / 8, 256>>>(qkv, ksum, z);

    // 5) attn[b,n,e] = z[b,n] * sum_d Q[b,n,d] * kvT[b,e,d]   (NT per batch, row-scale)
    gemm_nt<false, true, false><<<dim3(DIM / BN, NSEQ / BM, BATCH), 256>>>(
        qkv, QKVW, sQKV, kvT, DIM, sKV, attn, DIM, sAT, DIM, z, NSEQ, nullptr);

    // 6) out = attn @ Wout^T + bout
    gemm_nt<false, false, true><<<dim3(DIM / BN, MTOT / BM, 1), 256>>>(
        attn, DIM, 0, Wout, DIM, 0, out, DIM, 0, DIM, nullptr, 0, bout);
}

// round 2
// speedup vs baseline: 1.0024x; 1.0024x over previous
#include <cuda_runtime.h>
#include <cstdint>

#define EPSF 1e-6f

static constexpr int BATCH = 8;
static constexpr int NSEQ  = 4096;
static constexpr int DIM   = 1024;
static constexpr int MTOT  = BATCH * NSEQ;   // 32768
static constexpr int QKVW  = 3 * DIM;        // 3072

// ---------------- scratch (alloc-free rule: __device__ globals) ----------------
__device__ float g_qkv [(size_t)MTOT * QKVW];     // ~402 MB
__device__ float g_kvT [(size_t)BATCH * DIM * DIM];
__device__ float g_attn[(size_t)MTOT * DIM];
__device__ float g_ksum[BATCH * DIM];
__device__ float g_z   [MTOT];

// ---------------- tf32 helpers ----------------
__device__ __forceinline__ uint32_t f2tf32(float f) {
    uint32_t r;
    asm("cvt.rna.tf32.f32 %0, %1;" : "=r"(r) : "f"(f));
    return r;
}

__device__ __forceinline__ void mma_tf32(float c[4],
                                         uint32_t a0, uint32_t a1, uint32_t a2, uint32_t a3,
                                         uint32_t b0, uint32_t b1) {
    asm volatile(
        "mma.sync.aligned.m16n8k8.row.col.f32.tf32.tf32.f32 "
        "{%0,%1,%2,%3},{%4,%5,%6,%7},{%8,%9},{%0,%1,%2,%3};\n"
        : "+f"(c[0]), "+f"(c[1]), "+f"(c[2]), "+f"(c[3])
        : "r"(a0), "r"(a1), "r"(a2), "r"(a3), "r"(b0), "r"(b1));
}

// ---------------- epilogue ----------------
template<bool RELU, bool SCALE, bool BIAS>
__device__ __forceinline__ void store_pair(float* C, int ldc, int row, int col,
                                           float v0, float v1,
                                           const float* rowScale, const float* bias) {
    if (SCALE) { float s = rowScale[row]; v0 *= s; v1 *= s; }
    if (RELU) {
        if (col < 2 * DIM) {            // q and k segments get relu + eps; v untouched
            v0 = fmaxf(v0, 0.f) + EPSF;
            v1 = fmaxf(v1, 0.f) + EPSF;
        }
    }
    if (BIAS) { v0 += bias[col]; v1 += bias[col + 1]; }
    *reinterpret_cast<float2*>(C + (long long)row * ldc + col) = make_float2(v0, v1);
}

// =====================================================================
// NT GEMM: C[M,N] = A[M,K] (row-major, lda) * Bt[N,K]^T (row-major, ldb)
// Block tile 128x128, BK=16, 8 warps (2x4), warp tile 64x32.
// tf32x3 split for ~fp32 accuracy.
// =====================================================================
#define BM 128
#define BN 128
#define BK 16
#define LDS_NT (BK + 4)     // 20 floats: conflict-free, 16B-aligned rows (80B)

template<bool RELU, bool SCALE, bool BIAS>
__global__ __launch_bounds__(256, 2)
void gemm_nt(const float* __restrict__ A, int lda, long long strideA,
             const float* __restrict__ Bt, int ldb, long long strideB,
             float* __restrict__ C, int ldc, long long strideC,
             int K,
             const float* __restrict__ rowScale, long long strideScale,
             const float* __restrict__ bias)
{
    __shared__ uint32_t AsH[BM][LDS_NT], AsL[BM][LDS_NT];
    __shared__ uint32_t BsH[BN][LDS_NT], BsL[BN][LDS_NT];

    const int tid  = threadIdx.x;
    const int wid  = tid >> 5;
    const int lane = tid & 31;
    const int g    = lane >> 2;      // groupID
    const int t    = lane & 3;       // thread-in-group
    const int warpM = (wid >> 2) * 64;
    const int warpN = (wid & 3) * 32;
    const int m0 = blockIdx.y * BM;
    const int n0 = blockIdx.x * BN;
    const int bz = blockIdx.z;

    A  += (long long)bz * strideA;
    Bt += (long long)bz * strideB;
    C  += (long long)bz * strideC;
    if (SCALE) rowScale += (long long)bz * strideScale;

    float acc[4][4][4];
    #pragma unroll
    for (int i = 0; i < 4; i++)
        #pragma unroll
        for (int j = 0; j < 4; j++)
            #pragma unroll
            for (int r = 0; r < 4; r++) acc[i][j][r] = 0.f;

    for (int kt = 0; kt < K; kt += BK) {
        // Load A & Bt tiles: each 128x16 = 512 float4, 256 threads -> 2 iters
        #pragma unroll
        for (int it = 0; it < 2; it++) {
            int i  = tid + it * 256;
            int m  = i >> 2;
            int k4 = (i & 3) * 4;
            float4 va = *reinterpret_cast<const float4*>(A + (long long)(m0 + m) * lda + kt + k4);
            float4 vb = *reinterpret_cast<const float4*>(Bt + (long long)(n0 + m) * ldb + kt + k4);
            float fa[4] = {va.x, va.y, va.z, va.w};
            float fb[4] = {vb.x, vb.y, vb.z, vb.w};
            uint32_t ah[4], al[4], bh[4], bl[4];
            #pragma unroll
            for (int j = 0; j < 4; j++) {
                ah[j] = f2tf32(fa[j]); al[j] = f2tf32(fa[j] - __uint_as_float(ah[j]));
                bh[j] = f2tf32(fb[j]); bl[j] = f2tf32(fb[j] - __uint_as_float(bh[j]));
            }
            *reinterpret_cast<uint4*>(&AsH[m][k4]) = make_uint4(ah[0], ah[1], ah[2], ah[3]);
            *reinterpret_cast<uint4*>(&AsL[m][k4]) = make_uint4(al[0], al[1], al[2], al[3]);
            *reinterpret_cast<uint4*>(&BsH[m][k4]) = make_uint4(bh[0], bh[1], bh[2], bh[3]);
            *reinterpret_cast<uint4*>(&BsL[m][k4]) = make_uint4(bl[0], bl[1], bl[2], bl[3]);
        }
        __syncthreads();

        #pragma unroll
        for (int kk = 0; kk < BK; kk += 8) {
            uint32_t ah[4][4], al[4][4];
            #pragma unroll
            for (int mi = 0; mi < 4; mi++) {
                int r = warpM + mi * 16 + g;
                ah[mi][0] = AsH[r    ][kk + t];
                ah[mi][1] = AsH[r + 8][kk + t];
                ah[mi][2] = AsH[r    ][kk + t + 4];
                ah[mi][3] = AsH[r + 8][kk + t + 4];
                al[mi][0] = AsL[r    ][kk + t];
                al[mi][1] = AsL[r + 8][kk + t];
                al[mi][2] = AsL[r    ][kk + t + 4];
                al[mi][3] = AsL[r + 8][kk + t + 4];
            }
            #pragma unroll
            for (int ni = 0; ni < 4; ni++) {
                int c = warpN + ni * 8 + g;
                uint32_t bh0 = BsH[c][kk + t], bh1 = BsH[c][kk + t + 4];
                uint32_t bl0 = BsL[c][kk + t], bl1 = BsL[c][kk + t + 4];
                #pragma unroll
                for (int mi = 0; mi < 4; mi++) {
                    mma_tf32(acc[mi][ni], ah[mi][0], ah[mi][1], ah[mi][2], ah[mi][3], bh0, bh1);
                    mma_tf32(acc[mi][ni], ah[mi][0], ah[mi][1], ah[mi][2], ah[mi][3], bl0, bl1);
                    mma_tf32(acc[mi][ni], al[mi][0], al[mi][1], al[mi][2], al[mi][3], bh0, bh1);
                }
            }
        }
        __syncthreads();
    }

    // Epilogue
    #pragma unroll
    for (int mi = 0; mi < 4; mi++) {
        int r0 = m0 + warpM + mi * 16 + g;
        #pragma unroll
        for (int ni = 0; ni < 4; ni++) {
            int c0 = n0 + warpN + ni * 8 + 2 * t;
            store_pair<RELU, SCALE, BIAS>(C, ldc, r0,     c0, acc[mi][ni][0], acc[mi][ni][1], rowScale, bias);
            store_pair<RELU, SCALE, BIAS>(C, ldc, r0 + 8, c0, acc[mi][ni][2], acc[mi][ni][3], rowScale, bias);
        }
    }
}

// =====================================================================
// TN GEMM: C[M,N] = sum_k A[k,M] * B[k,N]   (A,B row-major over k, lda/ldb)
// Used for kvT[e,d] = sum_n V[n,e] * K[n,d]
// =====================================================================
#define LDS_TN (BM + 8)   // 136: conflict-free, rows 544B = 34*16B

__global__ __launch_bounds__(256, 2)
void gemm_tn(const float* __restrict__ A, int lda, long long strideA,
             const float* __restrict__ B, int ldb, long long strideB,
             float* __restrict__ C, int ldc, long long strideC,
             int K)
{
    __shared__ uint32_t AsH[BK][LDS_TN], AsL[BK][LDS_TN];
    __shared__ uint32_t BsH[BK][LDS_TN], BsL[BK][LDS_TN];

    const int tid  = threadIdx.x;
    const int wid  = tid >> 5;
    const int lane = tid & 31;
    const int g    = lane >> 2;
    const int t    = lane & 3;
    const int warpM = (wid >> 2) * 64;
    const int warpN = (wid & 3) * 32;
    const int m0 = blockIdx.y * BM;
    const int n0 = blockIdx.x * BN;
    const int bz = blockIdx.z;

    A += (long long)bz * strideA;
    B += (long long)bz * strideB;
    C += (long long)bz * strideC;

    float acc[4][4][4];
    #pragma unroll
    for (int i = 0; i < 4; i++)
        #pragma unroll
        for (int j = 0; j < 4; j++)
            #pragma unroll
            for (int r = 0; r < 4; r++) acc[i][j][r] = 0.f;

    for (int kt = 0; kt < K; kt += BK) {
        // Tiles: 16 rows(k) x 128 cols(m/n) = 512 float4 each; 2 iters
        #pragma unroll
        for (int it = 0; it < 2; it++) {
            int i  = tid + it * 256;
            int k  = i >> 5;
            int m4 = (i & 31) * 4;
            float4 va = *reinterpret_cast<const float4*>(A + (long long)(kt + k) * lda + m0 + m4);
            float4 vb = *reinterpret_cast<const float4*>(B + (long long)(kt + k) * ldb + n0 + m4);
            float fa[4] = {va.x, va.y, va.z, va.w};
            float fb[4] = {vb.x, vb.y, vb.z, vb.w};
            uint32_t ah[4], al[4], bh[4], bl[4];
            #pragma unroll
            for (int j = 0; j < 4; j++) {
                ah[j] = f2tf32(fa[j]); al[j] = f2tf32(fa[j] - __uint_as_float(ah[j]));
                bh[j] = f2tf32(fb[j]); bl[j] = f2tf32(fb[j] - __uint_as_float(bh[j]));
            }
            *reinterpret_cast<uint4*>(&AsH[k][m4]) = make_uint4(ah[0], ah[1], ah[2], ah[3]);
            *reinterpret_cast<uint4*>(&AsL[k][m4]) = make_uint4(al[0], al[1], al[2], al[3]);
            *reinterpret_cast<uint4*>(&BsH[k][m4]) = make_uint4(bh[0], bh[1], bh[2], bh[3]);
            *reinterpret_cast<uint4*>(&BsL[k][m4]) = make_uint4(bl[0], bl[1], bl[2], bl[3]);
        }
        __syncthreads();

        #pragma unroll
        for (int kk = 0; kk < BK; kk += 8) {
            uint32_t ah[4][4], al[4][4];
            #pragma unroll
            for (int mi = 0; mi < 4; mi++) {
                int r = warpM + mi * 16 + g;
                ah[mi][0] = AsH[kk + t    ][r    ];
                ah[mi][1] = AsH[kk + t    ][r + 8];
                ah[mi][2] = AsH[kk + t + 4][r    ];
                ah[mi][3] = AsH[kk + t + 4][r + 8];
                al[mi][0] = AsL[kk + t    ][r    ];
                al[mi][1] = AsL[kk + t    ][r + 8];
                al[mi][2] = AsL[kk + t + 4][r    ];
                al[mi][3] = AsL[kk + t + 4][r + 8];
            }
            #pragma unroll
            for (int ni = 0; ni < 4; ni++) {
                int c = warpN + ni * 8 + g;
                uint32_t bh0 = BsH[kk + t][c], bh1 = BsH[kk + t + 4][c];
                uint32_t bl0 = BsL[kk + t][c], bl1 = BsL[kk + t + 4][c];
                #pragma unroll
                for (int mi = 0; mi < 4; mi++) {
                    mma_tf32(acc[mi][ni], ah[mi][0], ah[mi][1], ah[mi][2], ah[mi][3], bh0, bh1);
                    mma_tf32(acc[mi][ni], ah[mi][0], ah[mi][1], ah[mi][2], ah[mi][3], bl0, bl1);
                    mma_tf32(acc[mi][ni], al[mi][0], al[mi][1], al[mi][2], al[mi][3], bh0, bh1);
                }
            }
        }
        __syncthreads();
    }

    #pragma unroll
    for (int mi = 0; mi < 4; mi++) {
        int r0 = m0 + warpM + mi * 16 + g;
        #pragma unroll
        for (int ni = 0; ni < 4; ni++) {
            int c0 = n0 + warpN + ni * 8 + 2 * t;
            *reinterpret_cast<float2*>(C + (long long)r0 * ldc + c0) =
                make_float2(acc[mi][ni][0], acc[mi][ni][1]);
            *reinterpret_cast<float2*>(C + (long long)(r0 + 8) * ldc + c0) =
                make_float2(acc[mi][ni][2], acc[mi][ni][3]);
        }
    }
}

// ---------------- ksum[b,d] = sum_n k[b,n,d] (k = qkv cols [1024,2048)) ----------------
__global__ void ksum_kernel(const float* __restrict__ qkv, float* __restrict__ ksum)
{
    int d = blockIdx.x * 256 + threadIdx.x;
    int b = blockIdx.y;
    const float* base = qkv + (long long)b * NSEQ * QKVW + DIM + d;
    float s = 0.f;
    #pragma unroll 8
    for (int n = 0; n < NSEQ; n++) s += base[(long long)n * QKVW];
    ksum[b * DIM + d] = s;
}

// ---------------- z[b,n] = 1/(dot(q[b,n,:], ksum[b,:]) + eps) ----------------
__global__ void z_kernel(const float* __restrict__ qkv, const float* __restrict__ ksum,
                         float* __restrict__ z)
{
    int row  = blockIdx.x * 8 + (threadIdx.x >> 5);   // one warp per row
    int lane = threadIdx.x & 31;
    int b = row >> 12;                                 // row / 4096
    const float* q  = qkv + (long long)row * QKVW;     // q segment at col 0
    const float* ks = ksum + b * DIM;
    float s = 0.f;
    #pragma unroll 8
    for (int i = lane; i < DIM; i += 32) s += q[i] * ks[i];
    #pragma unroll
    for (int o = 16; o > 0; o >>= 1) s += __shfl_xor_sync(0xFFFFFFFFu, s, o);
    if (lane == 0) z[row] = 1.f / (s + EPSF);
}

// =====================================================================
extern "C" void kernel_launch(void* const* d_in, const int* in_sizes, int n_in,
                              void* d_out, int out_size)
{
    const float* x    = (const float*)d_in[0];   // [8,4096,1024]
    const float* Wqkv = (const float*)d_in[1];   // [3072,1024]
    const float* Wout = (const float*)d_in[2];   // [1024,1024]
    const float* bout = (const float*)d_in[3];   // [1024]
    float* out = (float*)d_out;                  // [8,4096,1024]

    float *qkv, *kvT, *attn, *ksum, *z;
    cudaGetSymbolAddress((void**)&qkv,  g_qkv);
    cudaGetSymbolAddress((void**)&kvT,  g_kvT);
    cudaGetSymbolAddress((void**)&attn, g_attn);
    cudaGetSymbolAddress((void**)&ksum, g_ksum);
    cudaGetSymbolAddress((void**)&z,    g_z);

    const long long sQKV = (long long)NSEQ * QKVW;   // per-batch qkv stride
    const long long sKV  = (long long)DIM * DIM;
    const long long sAT  = (long long)NSEQ * DIM;

    // 1) qkv = x @ Wqkv^T, relu+eps on q,k segments
    gemm_nt<true, false, false><<<dim3(QKVW / BN, MTOT / BM, 1), 256>>>(
        x, DIM, 0, Wqkv, DIM, 0, qkv, QKVW, 0, DIM, nullptr, 0, nullptr);

    // 2) ksum[b,d]
    ksum_kernel<<<dim3(DIM / 256, BATCH), 256>>>(qkv, ksum);

    // 3) kvT[b,e,d] = sum_n V[b,n,e] * K[b,n,d]   (TN, per batch)
    gemm_tn<<<dim3(DIM / BN, DIM / BM, BATCH), 256>>>(
        qkv + 2 * DIM, QKVW, sQKV,     // A = V
        qkv + DIM,     QKVW, sQKV,     // B = K
        kvT, DIM, sKV, NSEQ);

    // 4) z[b,n]
    z_kernel<<<MTOT / 8, 256>>>(qkv, ksum, z);

    // 5) attn[b,n,e] = z[b,n] * sum_d Q[b,n,d] * kvT[b,e,d]   (NT per batch, row-scale)
    gemm_nt<false, true, false><<<dim3(DIM / BN, NSEQ / BM, BATCH), 256>>>(
        qkv, QKVW, sQKV, kvT, DIM, sKV, attn, DIM, sAT, DIM, z, NSEQ, nullptr);

    // 6) out = attn @ Wout^T + bout
    gemm_nt<false, false, true><<<dim3(DIM / BN, MTOT / BM, 1), 256>>>(
        attn, DIM, 0, Wout, DIM, 0, out, DIM, 0, DIM, nullptr, 0, bout);
}

// round 6
// speedup vs baseline: 1.4057x; 1.4024x over previous
#include <cuda_runtime.h>
#include <cuda_bf16.h>
#include <cstdint>

using bf16 = __nv_bfloat16;
#define EPSF 1e-6f
static constexpr int BATCH=8, NSEQ=4096, DIM=1024, MTOT=BATCH*NSEQ, QKVW=3*DIM;

__device__ float g_qkv [(size_t)MTOT*QKVW];
__device__ float g_kvT [(size_t)BATCH*DIM*DIM];
__device__ float g_attn[(size_t)MTOT*DIM];
__device__ float g_ksum[BATCH*DIM];
__device__ float g_z   [MTOT];

__device__ __forceinline__ uint32_t smem_u32(const void* p){
  uint32_t a; asm("{ .reg .u64 t; cvta.to.shared.u64 t, %1; cvt.u32.u64 %0, t; }":"=r"(a):"l"(p)); return a;
}
__device__ __forceinline__ void cpasync16(uint32_t dst, const void* src){
  asm volatile("cp.async.cg.shared.global [%0], [%1], 16;"::"r"(dst),"l"(src));
}
#define CP_COMMIT() asm volatile("cp.async.commit_group;":::"memory")
#define CP_WAIT0()  asm volatile("cp.async.wait_group 0;":::"memory")
__device__ __forceinline__ void ldmx4(uint32_t* r, uint32_t addr){
  asm volatile("ldmatrix.sync.aligned.m8n8.x4.shared.b16 {%0,%1,%2,%3}, [%4];"
    :"=r"(r[0]),"=r"(r[1]),"=r"(r[2]),"=r"(r[3]):"r"(addr));
}
__device__ __forceinline__ void mma16816(float* c, const uint32_t* a, uint32_t b0, uint32_t b1){
  asm volatile("mma.sync.aligned.m16n8k16.row.col.f32.bf16.bf16.f32 "
    "{%0,%1,%2,%3},{%4,%5,%6,%7},{%8,%9},{%0,%1,%2,%3};"
    :"+f"(c[0]),"+f"(c[1]),"+f"(c[2]),"+f"(c[3])
    :"r"(a[0]),"r"(a[1]),"r"(a[2]),"r"(a[3]),"r"(b0),"r"(b1));
}
__device__ __forceinline__ uint2 pack_h(const float* f){
  union{uint2 u; bf16 b[4];} H;
  #pragma unroll
  for(int k=0;k<4;k++) H.b[k]=__float2bfloat16_rn(f[k]);
  return H.u;
}
__device__ __forceinline__ uint2 pack_l(const float* f){
  union{uint2 u; bf16 b[4];} L;
  #pragma unroll
  for(int k=0;k<4;k++){ bf16 h=__float2bfloat16_rn(f[k]); L.b[k]=__float2bfloat16_rn(f[k]-__bfloat162float(h)); }
  return L.u;
}

// SMEM layout (dynamic):
//  bf16 planes: buf b at b*40960: AH +0, AL +10240, BH +20480, BL +30720  (128 rows x 80B)
//  fp32 stage : 81920 + b*32768: SA 16KB, SB 16KB
static constexpr int PL = 10240, BUFS = 40960, STAGE0 = 81920, SMEM_DYN = 147456;

// C[M,N] = A[M,K]*B[N,K]^T (bf16x3). TRANS: sources are [K,*] with * contiguous.
// EPI: 0=relu+eps on cols<2048, 1=plain, 2=row-scale, 3=+bias
template<bool TRANS, int EPI>
__global__ __launch_bounds__(256,1)
void hgemm(const float* __restrict__ Ag, long long ldA, long long bsA,
           const float* __restrict__ Bg, long long ldB, long long bsB, int K,
           float* __restrict__ Cg, long long ldC, long long bsC,
           const float* __restrict__ rowScale, long long bsS,
           const float* __restrict__ bias)
{
  extern __shared__ char sm[];
  const uint32_t smb = smem_u32(sm);
  const int tid=threadIdx.x, wid=tid>>5, lane=tid&31, bz=blockIdx.z;
  Ag += (size_t)bz*bsA; Bg += (size_t)bz*bsB; Cg += (size_t)bz*bsC;
  if(EPI==2) rowScale += (size_t)bz*bsS;
  const int row0 = blockIdx.y*128, col0 = blockIdx.x*128;
  const int warpM = (wid>>2)*64, warpN = (wid&3)*32;
  const int NS = K>>5;

  float acc[4][4][4];
  #pragma unroll
  for(int i=0;i<4;i++)
    #pragma unroll
    for(int j=0;j<4;j++){ acc[i][j][0]=0.f;acc[i][j][1]=0.f;acc[i][j][2]=0.f;acc[i][j][3]=0.f; }

  // ---- cp.async issue of fp32 tile s into stage[st] ----
  auto issue = [&](int s, int st){
    const size_t kt = (size_t)s*32;
    const uint32_t sa = smb + STAGE0 + st*32768, sb = sa + 16384;
    if(!TRANS){
      #pragma unroll
      for(int i=0;i<4;i++){ int p=tid+i*256, r=p>>3, c4=p&7;
        cpasync16(sa+p*16, Ag + (size_t)(row0+r)*ldA + kt + c4*4);
        cpasync16(sb+p*16, Bg + (size_t)(col0+r)*ldB + kt + c4*4); }
    } else {
      #pragma unroll
      for(int i=0;i<4;i++){ int p=tid+i*256, nr=p>>5, e4=p&31;
        cpasync16(sa+p*16, Ag + (kt+nr)*ldA + row0 + e4*4);
        cpasync16(sb+p*16, Bg + (kt+nr)*ldB + col0 + e4*4); }
    }
    CP_COMMIT();
  };
  // ---- convert stage[st] -> bf16 planes buf[st] ----
  auto convert = [&](int st){
    const float* SA = (const float*)(sm + STAGE0 + st*32768);
    const float* SB = SA + 4096;
    char* base = sm + st*BUFS;
    if(!TRANS){
      #pragma unroll
      for(int i=0;i<4;i++){ int p=tid+i*256, r=p>>3, c4=p&7;
        float4 va = ((const float4*)SA)[p];
        float4 vb = ((const float4*)SB)[p];
        float fa[4]={va.x,va.y,va.z,va.w}, fb[4]={vb.x,vb.y,vb.z,vb.w};
        uint32_t off = r*80 + c4*8;
        *(uint2*)(base + off)         = pack_h(fa);
        *(uint2*)(base + PL + off)    = pack_l(fa);
        *(uint2*)(base + 2*PL + off)  = pack_h(fb);
        *(uint2*)(base + 3*PL + off)  = pack_l(fb);
      }
    } else {
      #pragma unroll
      for(int i=0;i<4;i++){
        int n4 = (tid>>7) + i*2, e = tid&127;
        float fa[4], fb[4];
        #pragma unroll
        for(int j=0;j<4;j++){ fa[j]=SA[(n4*4+j)*128+e]; fb[j]=SB[(n4*4+j)*128+e]; }
        uint32_t off = e*80 + n4*8;
        *(uint2*)(base + off)         = pack_h(fa);
        *(uint2*)(base + PL + off)    = pack_l(fa);
        *(uint2*)(base + 2*PL + off)  = pack_h(fb);
        *(uint2*)(base + 3*PL + off)  = pack_l(fb);
      }
    }
  };
  // ---- MMA over buf b ----
  const uint32_t laneOff = ((lane&7) + ((lane>>3)&1)*8)*80 + (lane>>4)*16;
  auto domma = [&](int b){
    const uint32_t base = smb + b*BUFS;
    const uint32_t aH0 = base + warpM*80 + laneOff;
    const uint32_t bH0 = base + 2*PL + warpN*80 + laneOff;
    #pragma unroll
    for(int k16=0;k16<2;k16++){
      const uint32_t ko = k16*32;
      uint32_t aH[4][4], aL[4][4], bH[4][2], bL[4][2];
      #pragma unroll
      for(int mi=0;mi<4;mi++){
        ldmx4(aH[mi], aH0 + mi*1280 + ko);
        ldmx4(aL[mi], aH0 + PL + mi*1280 + ko);
      }
      #pragma unroll
      for(int np=0;np<2;np++){
        uint32_t r[4];
        ldmx4(r, bH0 + np*1280 + ko);
        bH[np*2][0]=r[0]; bH[np*2+1][0]=r[1]; bH[np*2][1]=r[2]; bH[np*2+1][1]=r[3];
        ldmx4(r, bH0 + PL + np*1280 + ko);
        bL[np*2][0]=r[0]; bL[np*2+1][0]=r[1]; bL[np*2][1]=r[2]; bL[np*2+1][1]=r[3];
      }
      #pragma unroll
      for(int mi=0;mi<4;mi++)
        #pragma unroll
        for(int ni=0;ni<4;ni++){
          mma16816(acc[mi][ni], aH[mi], bH[ni][0], bH[ni][1]);
          mma16816(acc[mi][ni], aH[mi], bL[ni][0], bL[ni][1]);
          mma16816(acc[mi][ni], aL[mi], bH[ni][0], bH[ni][1]);
        }
    }
  };

  // prologue
  issue(0, 0);
  CP_WAIT0(); __syncthreads();
  convert(0); __syncthreads();
  for(int s=0;s<NS;++s){
    if(s+1<NS) issue(s+1, (s+1)&1);
    domma(s&1);
    if(s+1<NS){
      CP_WAIT0(); __syncthreads();
      convert((s+1)&1);
      __syncthreads();
    }
  }

  // epilogue
  #pragma unroll
  for(int mi=0;mi<4;mi++){
    const int r0 = row0 + warpM + mi*16 + (lane>>2);
    float s0=1.f, s1=1.f;
    if(EPI==2){ s0=rowScale[r0]; s1=rowScale[r0+8]; }
    #pragma unroll
    for(int ni=0;ni<4;ni++){
      const int c = col0 + warpN + ni*8 + 2*(lane&3);
      float v0=acc[mi][ni][0], v1=acc[mi][ni][1], v2=acc[mi][ni][2], v3=acc[mi][ni][3];
      if(EPI==0 && c<2048){
        v0=fmaxf(v0,0.f)+EPSF; v1=fmaxf(v1,0.f)+EPSF;
        v2=fmaxf(v2,0.f)+EPSF; v3=fmaxf(v3,0.f)+EPSF;
      }
      if(EPI==2){ v0*=s0; v1*=s0; v2*=s1; v3*=s1; }
      if(EPI==3){ float b0=bias[c], b1=bias[c+1]; v0+=b0; v1+=b1; v2+=b0; v3+=b1; }
      *(float2*)(Cg + (size_t)r0*ldC + c)     = make_float2(v0,v1);
      *(float2*)(Cg + (size_t)(r0+8)*ldC + c) = make_float2(v2,v3);
    }
  }
}

__global__ void ksum_zero(float* ks){ ks[blockIdx.x*256+threadIdx.x]=0.f; }
__global__ void ksum_kernel(const float* __restrict__ qkv, float* __restrict__ ks){
  int d=blockIdx.x*256+threadIdx.x, b=blockIdx.y, nz=blockIdx.z;
  const float* base = qkv + (size_t)b*NSEQ*QKVW + (size_t)nz*512*QKVW + DIM + d;
  float s=0.f;
  #pragma unroll 8
  for(int n=0;n<512;n++) s += base[(size_t)n*QKVW];
  atomicAdd(&ks[b*DIM+d], s);
}
__global__ void z_kernel(const float* __restrict__ qkv, const float* __restrict__ ks, float* __restrict__ z){
  int row=blockIdx.x*8+(threadIdx.x>>5), lane=threadIdx.x&31, b=row>>12;
  const float* q = qkv + (size_t)row*QKVW;
  const float* kp = ks + b*DIM;
  float s=0.f;
  #pragma unroll 8
  for(int i=lane;i<DIM;i+=32) s += q[i]*kp[i];
  #pragma unroll
  for(int o=16;o>0;o>>=1) s += __shfl_xor_sync(0xFFFFFFFFu,s,o);
  if(lane==0) z[row]=1.f/(s+EPSF);
}

extern "C" void kernel_launch(void* const* d_in, const int* in_sizes, int n_in,
                              void* d_out, int out_size)
{
  const float* x    = (const float*)d_in[0];
  const float* Wqkv = (const float*)d_in[1];
  const float* Wout = (const float*)d_in[2];
  const float* bout = (const float*)d_in[3];
  float* out = (float*)d_out;
  float *qkv,*kvT,*attn,*ksum,*z;
  cudaGetSymbolAddress((void**)&qkv,g_qkv);
  cudaGetSymbolAddress((void**)&kvT,g_kvT);
  cudaGetSymbolAddress((void**)&attn,g_attn);
  cudaGetSymbolAddress((void**)&ksum,g_ksum);
  cudaGetSymbolAddress((void**)&z,g_z);
  cudaFuncSetAttribute(hgemm<false,0>, cudaFuncAttributeMaxDynamicSharedMemorySize, SMEM_DYN);
  cudaFuncSetAttribute(hgemm<true ,1>, cudaFuncAttributeMaxDynamicSharedMemorySize, SMEM_DYN);
  cudaFuncSetAttribute(hgemm<false,2>, cudaFuncAttributeMaxDynamicSharedMemorySize, SMEM_DYN);
  cudaFuncSetAttribute(hgemm<false,3>, cudaFuncAttributeMaxDynamicSharedMemorySize, SMEM_DYN);
  const long long sQ=(long long)NSEQ*QKVW, sKV=(long long)DIM*DIM, sA=(long long)NSEQ*DIM;
  // 1) qkv = x @ Wqkv^T, relu+eps on q,k
  hgemm<false,0><<<dim3(QKVW/128, MTOT/128, 1),256,SMEM_DYN>>>(
      x, DIM,0, Wqkv, DIM,0, DIM, qkv, QKVW,0, nullptr,0, nullptr);
  // 2) ksum
  ksum_zero<<<32,256>>>(ksum);
  ksum_kernel<<<dim3(DIM/256,BATCH,8),256>>>(qkv,ksum);
  // 3) kvT[b,e,d] = sum_n V[n,e]K[n,d]  (transposing loaders)
  hgemm<true,1><<<dim3(DIM/128, DIM/128, BATCH),256,SMEM_DYN>>>(
      qkv+2*DIM, QKVW, sQ, qkv+DIM, QKVW, sQ, NSEQ, kvT, DIM, sKV, nullptr,0, nullptr);
  // 4) z
  z_kernel<<<MTOT/8,256>>>(qkv,ksum,z);
  // 5) attn[n,e] = z[n] * Q[n,:]·kvT[e,:]
  hgemm<false,2><<<dim3(DIM/128, NSEQ/128, BATCH),256,SMEM_DYN>>>(
      qkv, QKVW, sQ, kvT, DIM, sKV, DIM, attn, DIM, sA, z, NSEQ, nullptr);
  // 6) out = attn @ Wout^T + b
  hgemm<false,3><<<dim3(DIM/128, MTOT/128, 1),256,SMEM_DYN>>>(
      attn, DIM,0, Wout, DIM,0, DIM, out, DIM,0, nullptr,0, bout);
}

// round 7
// speedup vs baseline: 1.9551x; 1.3908x over previous
#include <cuda_runtime.h>
#include <cuda_bf16.h>
#include <cstdint>

using bf16 = __nv_bfloat16;
#define EPSF 1e-6f
static constexpr int BATCH=8, NSEQ=4096, DIM=1024, MTOT=BATCH*NSEQ, QKVW=3*DIM;

// bf16 hi/lo plane scratch
__device__ alignas(256) bf16 g_xh [(size_t)MTOT*DIM];
__device__ alignas(256) bf16 g_xl [(size_t)MTOT*DIM];
__device__ alignas(256) bf16 g_wqh[(size_t)QKVW*DIM];
__device__ alignas(256) bf16 g_wql[(size_t)QKVW*DIM];
__device__ alignas(256) bf16 g_woh[(size_t)DIM*DIM];
__device__ alignas(256) bf16 g_wol[(size_t)DIM*DIM];
__device__ alignas(256) bf16 g_qkvh[(size_t)MTOT*QKVW];
__device__ alignas(256) bf16 g_qkvl[(size_t)MTOT*QKVW];
__device__ alignas(256) bf16 g_kvh[(size_t)BATCH*DIM*DIM];
__device__ alignas(256) bf16 g_kvl[(size_t)BATCH*DIM*DIM];
__device__ alignas(256) bf16 g_ath[(size_t)MTOT*DIM];
__device__ alignas(256) bf16 g_atl[(size_t)MTOT*DIM];
__device__ float g_ksum[BATCH*DIM];
__device__ float g_z   [MTOT];

__device__ __forceinline__ uint32_t smem_u32(const void* p){
  uint32_t a; asm("{ .reg .u64 t; cvta.to.shared.u64 t, %1; cvt.u32.u64 %0, t; }":"=r"(a):"l"(p)); return a;
}
__device__ __forceinline__ void cpasync16(uint32_t dst, const void* src){
  asm volatile("cp.async.cg.shared.global [%0], [%1], 16;"::"r"(dst),"l"(src));
}
#define CP_COMMIT() asm volatile("cp.async.commit_group;":::"memory")
#define CP_WAIT1()  asm volatile("cp.async.wait_group 1;":::"memory")
#define CP_WAIT0()  asm volatile("cp.async.wait_group 0;":::"memory")
__device__ __forceinline__ void ldmx4(uint32_t* r, uint32_t addr){
  asm volatile("ldmatrix.sync.aligned.m8n8.x4.shared.b16 {%0,%1,%2,%3}, [%4];"
    :"=r"(r[0]),"=r"(r[1]),"=r"(r[2]),"=r"(r[3]):"r"(addr));
}
__device__ __forceinline__ void ldmx4t(uint32_t* r, uint32_t addr){
  asm volatile("ldmatrix.sync.aligned.m8n8.x4.trans.shared.b16 {%0,%1,%2,%3}, [%4];"
    :"=r"(r[0]),"=r"(r[1]),"=r"(r[2]),"=r"(r[3]):"r"(addr));
}
__device__ __forceinline__ void mma16816(float* c, const uint32_t* a, uint32_t b0, uint32_t b1){
  asm volatile("mma.sync.aligned.m16n8k16.row.col.f32.bf16.bf16.f32 "
    "{%0,%1,%2,%3},{%4,%5,%6,%7},{%8,%9},{%0,%1,%2,%3};"
    :"+f"(c[0]),"+f"(c[1]),"+f"(c[2]),"+f"(c[3])
    :"r"(a[0]),"r"(a[1]),"r"(a[2]),"r"(a[3]),"r"(b0),"r"(b1));
}
__device__ __forceinline__ uint32_t pack2h(float v0, float v1){
  union{uint32_t u; bf16 b[2];} H; H.b[0]=__float2bfloat16_rn(v0); H.b[1]=__float2bfloat16_rn(v1); return H.u;
}
__device__ __forceinline__ uint32_t pack2l(float v0, float v1){
  union{uint32_t u; bf16 b[2];} L;
  bf16 h0=__float2bfloat16_rn(v0), h1=__float2bfloat16_rn(v1);
  L.b[0]=__float2bfloat16_rn(v0-__bfloat162float(h0));
  L.b[1]=__float2bfloat16_rn(v1-__bfloat162float(h1));
  return L.u;
}

// 3 stages x 64KB: per stage AH 0, AL 16K, BH 32K, BL 48K (tiles 128x128B or 64x256B)
static constexpr int STG = 65536, SMEM_DYN = 3*STG;

// C[M,N] = A[M,K]*B[N,K]^T (bf16x3, planes). TRANS: sources [K][*] contiguous, ldmatrix.trans.
// EPI: 0=relu+eps cols<2048 -> planes, 1=planes, 2=row-scale -> planes, 3=+bias -> fp32
template<bool TRANS, int EPI>
__global__ __launch_bounds__(256,1)
void hgemm(const bf16* __restrict__ Ah, const bf16* __restrict__ Al, long long ldA, long long bsA,
           const bf16* __restrict__ Bh, const bf16* __restrict__ Bl, long long ldB, long long bsB, int K,
           bf16* __restrict__ Ch, bf16* __restrict__ Cl, float* __restrict__ Cf, long long ldC, long long bsC,
           const float* __restrict__ rowScale, long long bsS,
           const float* __restrict__ bias)
{
  extern __shared__ char sm[];
  const uint32_t smb = smem_u32(sm);
  const int tid=threadIdx.x, wid=tid>>5, lane=tid&31, bz=blockIdx.z;
  Ah += (size_t)bz*bsA; Al += (size_t)bz*bsA;
  Bh += (size_t)bz*bsB; Bl += (size_t)bz*bsB;
  if(EPI==3) Cf += (size_t)bz*bsC; else { Ch += (size_t)bz*bsC; Cl += (size_t)bz*bsC; }
  if(EPI==2) rowScale += (size_t)bz*bsS;
  const int row0 = blockIdx.y*128, col0 = blockIdx.x*128;
  const int warpM = (wid>>2)*64, warpN = (wid&3)*32;
  const int NS = K>>6;

  float acc[4][4][4];
  #pragma unroll
  for(int i=0;i<4;i++)
    #pragma unroll
    for(int j=0;j<4;j++){ acc[i][j][0]=0.f;acc[i][j][1]=0.f;acc[i][j][2]=0.f;acc[i][j][3]=0.f; }

  auto issue = [&](int s, int st){
    const size_t kt = (size_t)s*64;
    const uint32_t bb = smb + st*STG;
    if(!TRANS){
      #pragma unroll
      for(int i=0;i<4;i++){
        int p=tid+i*256, r=p>>3, c=p&7;
        uint32_t sw = (uint32_t)r*128 + (uint32_t)((c ^ (r&7))<<4);
        const size_t ga = (size_t)(row0+r)*ldA + kt + c*8;
        const size_t gb = (size_t)(col0+r)*ldB + kt + c*8;
        cpasync16(bb +         sw, Ah + ga);
        cpasync16(bb + 16384 + sw, Al + ga);
        cpasync16(bb + 32768 + sw, Bh + gb);
        cpasync16(bb + 49152 + sw, Bl + gb);
      }
    } else {
      #pragma unroll
      for(int i=0;i<4;i++){
        int p=tid+i*256, r=p>>4, c=p&15;
        uint32_t sw = (uint32_t)r*256 + (uint32_t)((c ^ (r&7))<<4);
        const size_t ga = (kt+r)*ldA + row0 + c*8;
        const size_t gb = (kt+r)*ldB + col0 + c*8;
        cpasync16(bb +         sw, Ah + ga);
        cpasync16(bb + 16384 + sw, Al + ga);
        cpasync16(bb + 32768 + sw, Bh + gb);
        cpasync16(bb + 49152 + sw, Bl + gb);
      }
    }
    CP_COMMIT();
  };

  const uint32_t rowsel = (uint32_t)((lane&7) + ((lane>>3)&1)*8);
  auto domma = [&](int st){
    const uint32_t bb = smb + st*STG;
    #pragma unroll
    for(int kb=0;kb<4;kb++){
      uint32_t aH[4][4], aL[4][4];
      #pragma unroll
      for(int mi=0;mi<4;mi++){
        uint32_t ad;
        if(!TRANS){
          uint32_t c16 = (uint32_t)((2*kb + (lane>>4)) ^ (lane&7));
          ad = bb + (warpM + mi*16 + rowsel)*128 + (c16<<4);
        } else {
          uint32_t rk = (uint32_t)(kb*16 + (lane>>4)*8 + (lane&7));
          uint32_t c16 = (uint32_t)((((warpM+mi*16)>>3) + ((lane>>3)&1)) ^ (lane&7));
          ad = bb + rk*256 + (c16<<4);
        }
        if(!TRANS){ ldmx4(aH[mi], ad); ldmx4(aL[mi], ad+16384); }
        else      { ldmx4t(aH[mi], ad); ldmx4t(aL[mi], ad+16384); }
      }
      uint32_t bH[4][2], bL[4][2];
      #pragma unroll
      for(int np=0;np<2;np++){
        uint32_t ad;
        if(!TRANS){
          uint32_t c16 = (uint32_t)((2*kb + (lane>>4)) ^ (lane&7));
          ad = bb + 32768 + (warpN + np*16 + rowsel)*128 + (c16<<4);
        } else {
          uint32_t rk = (uint32_t)(kb*16 + (lane>>4)*8 + (lane&7));
          uint32_t c16 = (uint32_t)((((warpN+np*16)>>3) + ((lane>>3)&1)) ^ (lane&7));
          ad = bb + 32768 + rk*256 + (c16<<4);
        }
        uint32_t r[4];
        if(!TRANS) ldmx4(r, ad); else ldmx4t(r, ad);
        bH[np*2][0]=r[0]; bH[np*2+1][0]=r[1]; bH[np*2][1]=r[2]; bH[np*2+1][1]=r[3];
        if(!TRANS) ldmx4(r, ad+16384); else ldmx4t(r, ad+16384);
        bL[np*2][0]=r[0]; bL[np*2+1][0]=r[1]; bL[np*2][1]=r[2]; bL[np*2+1][1]=r[3];
      }
      #pragma unroll
      for(int mi=0;mi<4;mi++)
        #pragma unroll
        for(int ni=0;ni<4;ni++){
          mma16816(acc[mi][ni], aH[mi], bH[ni][0], bH[ni][1]);
          mma16816(acc[mi][ni], aH[mi], bL[ni][0], bL[ni][1]);
          mma16816(acc[mi][ni], aL[mi], bH[ni][0], bH[ni][1]);
        }
    }
  };

  issue(0,0);
  if(NS>1) issue(1,1);
  int st=0;
  for(int s=0;s<NS;++s){
    if(s < NS-1) CP_WAIT1(); else CP_WAIT0();
    __syncthreads();
    if(s+2<NS){ int st2 = st+2>=3 ? st-1 : st+2; issue(s+2, st2); }
    domma(st);
    st = (st+1==3)?0:st+1;
    __syncthreads();
  }

  #pragma unroll
  for(int mi=0;mi<4;mi++){
    const int r0 = row0 + warpM + mi*16 + (lane>>2);
    float s0=1.f, s1=1.f;
    if(EPI==2){ s0=rowScale[r0]; s1=rowScale[r0+8]; }
    #pragma unroll
    for(int ni=0;ni<4;ni++){
      const int c = col0 + warpN + ni*8 + 2*(lane&3);
      float v0=acc[mi][ni][0], v1=acc[mi][ni][1], v2=acc[mi][ni][2], v3=acc[mi][ni][3];
      if(EPI==0 && c<2048){
        v0=fmaxf(v0,0.f)+EPSF; v1=fmaxf(v1,0.f)+EPSF;
        v2=fmaxf(v2,0.f)+EPSF; v3=fmaxf(v3,0.f)+EPSF;
      }
      if(EPI==2){ v0*=s0; v1*=s0; v2*=s1; v3*=s1; }
      if(EPI==3){
        float b0=bias[c], b1=bias[c+1];
        *(float2*)(Cf + (size_t)r0*ldC + c)     = make_float2(v0+b0, v1+b1);
        *(float2*)(Cf + (size_t)(r0+8)*ldC + c) = make_float2(v2+b0, v3+b1);
      } else {
        *(uint32_t*)(Ch + (size_t)r0*ldC + c)     = pack2h(v0,v1);
        *(uint32_t*)(Cl + (size_t)r0*ldC + c)     = pack2l(v0,v1);
        *(uint32_t*)(Ch + (size_t)(r0+8)*ldC + c) = pack2h(v2,v3);
        *(uint32_t*)(Cl + (size_t)(r0+8)*ldC + c) = pack2l(v2,v3);
      }
    }
  }
}

__global__ void split_kernel(const float* __restrict__ src, bf16* __restrict__ h, bf16* __restrict__ l){
  size_t i = ((size_t)blockIdx.x*256 + threadIdx.x)*4;
  float4 v = *(const float4*)(src+i);
  float f[4]={v.x,v.y,v.z,v.w};
  union{uint2 u; bf16 b[4];} H,L;
  #pragma unroll
  for(int k=0;k<4;k++){ bf16 hh=__float2bfloat16_rn(f[k]); H.b[k]=hh; L.b[k]=__float2bfloat16_rn(f[k]-__bfloat162float(hh)); }
  *(uint2*)(h+i)=H.u; *(uint2*)(l+i)=L.u;
}
__global__ void ksum_zero(float* ks){ ks[blockIdx.x*256+threadIdx.x]=0.f; }
__global__ void ksum_kernel(const bf16* __restrict__ qh, const bf16* __restrict__ ql, float* __restrict__ ks){
  int d=blockIdx.x*256+threadIdx.x, b=blockIdx.y, nz=blockIdx.z;
  const size_t base = (size_t)b*NSEQ*QKVW + (size_t)nz*512*QKVW + DIM + d;
  float s=0.f;
  #pragma unroll 8
  for(int n=0;n<512;n++){
    size_t o = base + (size_t)n*QKVW;
    s += __bfloat162float(qh[o]) + __bfloat162float(ql[o]);
  }
  atomicAdd(&ks[b*DIM+d], s);
}
__global__ void z_kernel(const bf16* __restrict__ qh, const bf16* __restrict__ ql,
                         const float* __restrict__ ks, float* __restrict__ z){
  int row=blockIdx.x*8+(threadIdx.x>>5), lane=threadIdx.x&31, b=row>>12;
  const bf16* qhp = qh + (size_t)row*QKVW;
  const bf16* qlp = ql + (size_t)row*QKVW;
  const float* kp = ks + b*DIM;
  float s=0.f;
  #pragma unroll 8
  for(int i=lane;i<DIM;i+=32)
    s += (__bfloat162float(qhp[i])+__bfloat162float(qlp[i]))*kp[i];
  #pragma unroll
  for(int o=16;o>0;o>>=1) s += __shfl_xor_sync(0xFFFFFFFFu,s,o);
  if(lane==0) z[row]=1.f/(s+EPSF);
}

extern "C" void kernel_launch(void* const* d_in, const int* in_sizes, int n_in,
                              void* d_out, int out_size)
{
  const float* x    = (const float*)d_in[0];
  const float* Wqkv = (const float*)d_in[1];
  const float* Wout = (const float*)d_in[2];
  const float* bout = (const float*)d_in[3];
  float* out = (float*)d_out;
  bf16 *xh,*xl,*wqh,*wql,*woh,*wol,*qkvh,*qkvl,*kvh,*kvl,*ath,*atl;
  float *ksum,*z;
  cudaGetSymbolAddress((void**)&xh,g_xh);   cudaGetSymbolAddress((void**)&xl,g_xl);
  cudaGetSymbolAddress((void**)&wqh,g_wqh); cudaGetSymbolAddress((void**)&wql,g_wql);
  cudaGetSymbolAddress((void**)&woh,g_woh); cudaGetSymbolAddress((void**)&wol,g_wol);
  cudaGetSymbolAddress((void**)&qkvh,g_qkvh); cudaGetSymbolAddress((void**)&qkvl,g_qkvl);
  cudaGetSymbolAddress((void**)&kvh,g_kvh); cudaGetSymbolAddress((void**)&kvl,g_kvl);
  cudaGetSymbolAddress((void**)&ath,g_ath); cudaGetSymbolAddress((void**)&atl,g_atl);
  cudaGetSymbolAddress((void**)&ksum,g_ksum); cudaGetSymbolAddress((void**)&z,g_z);
  cudaFuncSetAttribute(hgemm<false,0>, cudaFuncAttributeMaxDynamicSharedMemorySize, SMEM_DYN);
  cudaFuncSetAttribute(hgemm<true ,1>, cudaFuncAttributeMaxDynamicSharedMemorySize, SMEM_DYN);
  cudaFuncSetAttribute(hgemm<false,2>, cudaFuncAttributeMaxDynamicSharedMemorySize, SMEM_DYN);
  cudaFuncSetAttribute(hgemm<false,3>, cudaFuncAttributeMaxDynamicSharedMemorySize, SMEM_DYN);
  const long long sQ=(long long)NSEQ*QKVW, sKV=(long long)DIM*DIM, sA=(long long)NSEQ*DIM;

  // 0) split inputs into bf16 hi/lo planes
  split_kernel<<<(MTOT*(size_t)DIM)/1024, 256>>>(x, xh, xl);
  split_kernel<<<((size_t)QKVW*DIM)/1024, 256>>>(Wqkv, wqh, wql);
  split_kernel<<<((size_t)DIM*DIM)/1024, 256>>>(Wout, woh, wol);
  // 1) qkv = x @ Wqkv^T, relu+eps on q,k  -> planes
  hgemm<false,0><<<dim3(QKVW/128, MTOT/128, 1),256,SMEM_DYN>>>(
      xh, xl, DIM,0, wqh, wql, DIM,0, DIM, qkvh, qkvl, nullptr, QKVW,0, nullptr,0, nullptr);
  // 2) ksum
  ksum_zero<<<32,256>>>(ksum);
  ksum_kernel<<<dim3(DIM/256,BATCH,8),256>>>(qkvh, qkvl, ksum);
  // 3) kvT[b,e,d] = sum_n V[n,e]K[n,d]  (ldmatrix.trans path) -> planes
  hgemm<true,1><<<dim3(DIM/128, DIM/128, BATCH),256,SMEM_DYN>>>(
      qkvh+2*DIM, qkvl+2*DIM, QKVW, sQ, qkvh+DIM, qkvl+DIM, QKVW, sQ, NSEQ,
      kvh, kvl, nullptr, DIM, sKV, nullptr,0, nullptr);
  // 4) z
  z_kernel<<<MTOT/8,256>>>(qkvh, qkvl, ksum, z);
  // 5) attn[n,e] = z[n] * Q[n,:]·kvT[e,:] -> planes
  hgemm<false,2><<<dim3(DIM/128, NSEQ/128, BATCH),256,SMEM_DYN>>>(
      qkvh, qkvl, QKVW, sQ, kvh, kvl, DIM, sKV, DIM,
      ath, atl, nullptr, DIM, sA, z, NSEQ, nullptr);
  // 6) out = attn @ Wout^T + b  -> fp32
  hgemm<false,3><<<dim3(DIM/128, MTOT/128, 1),256,SMEM_DYN>>>(
      ath, atl, DIM,0, woh, wol, DIM,0, DIM,
      nullptr, nullptr, out, DIM,0, nullptr,0, bout);
}